// round 17
// baseline (speedup 1.0000x reference)
#include <cuda_runtime.h>
#include <cuda_fp16.h>
#include <cstdint>

// Problem constants (fixed shapes for SoftAgg_8873402434226)
#define Bn 8
#define Nn 65536
#define Dn 512
#define Sn 512

// Scratch (sanctioned: __device__ globals)
__device__ float  g_denom[Sn * Bn * Dn];
__device__ float  g_ynum[Sn * Bn * Dn];
__device__ float  g_hy[Sn * Bn * Dn];
__device__ int    g_seg[Nn];
__device__ int    g_is64;
__device__ __align__(16) __half g_xh[(size_t)Bn * Nn * Dn];  // x in fp16 (0.5 GB)
__device__ __align__(16) __half g_wgh[Dn * Dn];              // Wg fp16
__device__ __align__(16) __half g_wfh[Dn * Dn];              // Wf fp16

// ---------------------------------------------------------------------------
__device__ __forceinline__ uint32_t smem_u32(const void* p) {
    uint32_t a;
    asm("{ .reg .u64 t; cvta.to.shared.u64 t, %1; cvt.u32.u64 %0, t; }" : "=r"(a) : "l"(p));
    return a;
}

__device__ __forceinline__ uint32_t pack_h2(float a, float b) {
    __half2 h = __floats2half2_rn(a, b);
    return *reinterpret_cast<uint32_t*>(&h);
}

__device__ __forceinline__ void mma_f16(float* c, const unsigned* a,
                                        unsigned b0, unsigned b1) {
    asm volatile(
        "mma.sync.aligned.m16n8k16.row.col.f32.f16.f16.f32 "
        "{%0,%1,%2,%3}, {%4,%5,%6,%7}, {%8,%9}, {%0,%1,%2,%3};"
        : "+f"(c[0]), "+f"(c[1]), "+f"(c[2]), "+f"(c[3])
        : "r"(a[0]), "r"(a[1]), "r"(a[2]), "r"(a[3]), "r"(b0), "r"(b1));
}

#define LDSM4(r0, r1, r2, r3, addr) \
    asm volatile("ldmatrix.sync.aligned.m8n8.x4.shared.b16 {%0,%1,%2,%3}, [%4];" \
                 : "=r"(r0), "=r"(r1), "=r"(r2), "=r"(r3) : "r"(addr))

#define CP_ASYNC16(dst, src) \
    asm volatile("cp.async.cg.shared.global [%0], [%1], 16;" :: "r"(dst), "l"(src))
#define CP_COMMIT() asm volatile("cp.async.commit_group;" ::: "memory")
#define CP_WAIT2()  asm volatile("cp.async.wait_group 2;" ::: "memory")

// ---------------------------------------------------------------------------
// Kernel 0: detect ix dtype
// ---------------------------------------------------------------------------
__global__ void detect_k(const int* __restrict__ ixw) {
    if (threadIdx.x == 0 && blockIdx.x == 0) {
        int z = 1;
        for (int i = 1; i < 128; i += 2)
            if (ixw[i] != 0) { z = 0; break; }
        g_is64 = z;
    }
}

// ---------------------------------------------------------------------------
// Kernel 1: seg ids + zero accumulators (fused)
// ---------------------------------------------------------------------------
__global__ void segzero_k(const int* __restrict__ ixw) {
    const int gid = blockIdx.x * 256 + threadIdx.x;     // 0..65535
    int v = g_is64 ? ixw[2 * gid] : ixw[gid];
    g_seg[gid] = v & (Sn - 1);
    float4 z = make_float4(0.f, 0.f, 0.f, 0.f);
    #pragma unroll
    for (int i = 0; i < 8; i++) {
        ((float4*)g_denom)[gid * 8 + i] = z;
        ((float4*)g_ynum)[gid * 8 + i]  = z;
    }
}

// ---------------------------------------------------------------------------
// Kernel 2: x, Wg, Wf -> fp16 (fused)
// ---------------------------------------------------------------------------
#define XBLOCKS ((int)(((size_t)Bn * Nn * Dn / 4) / 256))   // 262144

__global__ void xwcvt_k(const float4* __restrict__ x,
                        const float4* __restrict__ Wg, const float4* __restrict__ Wf) {
    if (blockIdx.x < XBLOCKS) {
        const size_t gi = (size_t)blockIdx.x * 256 + threadIdx.x;
        float4 v = x[gi];
        uint2 o;
        o.x = pack_h2(v.x, v.y);
        o.y = pack_h2(v.z, v.w);
        ((uint2*)g_xh)[gi] = o;
    } else {
        const int i = (blockIdx.x - XBLOCKS) * 256 + threadIdx.x;   // < Dn*Dn/4
        float4 g = Wg[i];
        uint2 og; og.x = pack_h2(g.x, g.y); og.y = pack_h2(g.z, g.w);
        ((uint2*)g_wgh)[i] = og;
        float4 f = Wf[i];
        uint2 of; of.x = pack_h2(f.x, f.y); of.y = pack_h2(f.z, f.w);
        ((uint2*)g_wfh)[i] = of;
    }
}

// ---------------------------------------------------------------------------
// Kernel 3 (main): fused dual fp16 GEMM + exp + atomics.
// 512 threads = 16 warps = 2(m) x 8(e); warp tile 64m x 16e x {g,f}.
// ldmatrix.x4 operand loads (conflict-free at 144B row stride).
// 3-stage cp.async pipeline, k-chunk 64.
// ---------------------------------------------------------------------------
#define KCH 64
#define AKSH 72                         // fp16 row stride (144 B)
#define A_H (128 * AKSH)                // 9216 halfs
#define B_H (256 * AKSH)                // 18432 halfs
#define STAGE_H (A_H + B_H)             // 27648 halfs = 55296 B
#define SMEM_TOTAL (3 * STAGE_H * 2)    // 165888 B

__global__ __launch_bounds__(512, 1)
void main_k(const float* __restrict__ bfv, const float* __restrict__ bgv)
{
    extern __shared__ __half smh[];
    const uint32_t sb = smem_u32(smh);

    const int tid  = threadIdx.x;
    const int lane = tid & 31;
    const int wid  = tid >> 5;           // 0..15
    const int lr   = lane >> 2, lq = lane & 3;
    const int l16  = lane & 15;
    const int lhalf = lane >> 4;         // 0/1
    const int wm   = wid & 1;            // m half (64 rows)
    const int we   = wid >> 1;           // e group of 16 (0..7)

    const int eb    = blockIdx.x * 128;  // e base
    const int row0  = blockIdx.y * 128;  // flattened row (b*N + n)
    const int b     = row0 >> 16;
    const int nbase = row0 & (Nn - 1);

    const int ar = tid >> 3, ac = tid & 7;   // staging coords (64 rows x 8 cols)

    // ldmatrix lane byte offsets (within a stage buffer)
    const uint32_t aoff = ((wm * 64 + l16) * AKSH + lhalf * 8) * 2;
    const uint32_t goff = (A_H + (we * 16 + l16) * AKSH + lhalf * 8) * 2;
    const uint32_t foff = goff + 128 * AKSH * 2;

    float cg[4][2][4], cf[4][2][4];
    #pragma unroll
    for (int mt = 0; mt < 4; mt++)
        #pragma unroll
        for (int nt = 0; nt < 2; nt++)
            #pragma unroll
            for (int r = 0; r < 4; r++) { cg[mt][nt][r] = 0.f; cf[mt][nt][r] = 0.f; }

    auto stage = [&](int kc, int bs) {
        const uint32_t base = sb + (uint32_t)bs * STAGE_H * 2;
        // A: 128 rows x 64 k fp16 (16B per cp.async), 2 row passes
        const __half* asrc = g_xh + (size_t)(row0 + ar) * Dn + kc * KCH + ac * 8;
        #pragma unroll
        for (int it = 0; it < 2; it++) {
            uint32_t dst = base + ((ar + it * 64) * AKSH + ac * 8) * 2;
            CP_ASYNC16(dst, asrc + (size_t)(it * 64) * Dn);
        }
        // B: 256 rows (Wg then Wf) x 64 k, 4 row passes
        #pragma unroll
        for (int it = 0; it < 4; it++) {
            int n = ar + it * 64;
            const __half* src = (n < 128)
                ? g_wgh + (size_t)(eb + n) * Dn + kc * KCH + ac * 8
                : g_wfh + (size_t)(eb + n - 128) * Dn + kc * KCH + ac * 8;
            uint32_t dst = base + (A_H + n * AKSH + ac * 8) * 2;
            CP_ASYNC16(dst, src);
        }
    };

    stage(0, 0); CP_COMMIT();
    stage(1, 1); CP_COMMIT();

    for (int kc = 0; kc < Dn / KCH; kc++) {
        if (kc + 2 < Dn / KCH) stage(kc + 2, (kc + 2) % 3);
        CP_COMMIT();                       // unconditional: keeps group count uniform
        CP_WAIT2();
        __syncthreads();

        const uint32_t bufb = sb + (uint32_t)(kc % 3) * STAGE_H * 2;

        #pragma unroll
        for (int kk = 0; kk < KCH / 16; kk++) {
            const uint32_t kb = kk * 32;   // 16 halfs = 32 bytes
            unsigned a[4][4];
            #pragma unroll
            for (int mt = 0; mt < 4; mt++)
                LDSM4(a[mt][0], a[mt][1], a[mt][2], a[mt][3],
                      bufb + aoff + mt * (16 * AKSH * 2) + kb);
            unsigned gq0, gq1, gq2, gq3, fq0, fq1, fq2, fq3;
            LDSM4(gq0, gq1, gq2, gq3, bufb + goff + kb);
            LDSM4(fq0, fq1, fq2, fq3, bufb + foff + kb);
            #pragma unroll
            for (int mt = 0; mt < 4; mt++) {
                mma_f16(cg[mt][0], a[mt], gq0, gq2);
                mma_f16(cg[mt][1], a[mt], gq1, gq3);
                mma_f16(cf[mt][0], a[mt], fq0, fq2);
                mma_f16(cf[mt][1], a[mt], fq1, fq3);
            }
        }
        __syncthreads();
    }

    // epilogue: bias, exp, atomic scatter
    float biasg[2][2], biasf[2][2];
    #pragma unroll
    for (int nt = 0; nt < 2; nt++)
        #pragma unroll
        for (int cc = 0; cc < 2; cc++) {
            const int col = eb + we * 16 + nt * 8 + 2 * lq + cc;
            biasg[nt][cc] = bgv[col];
            biasf[nt][cc] = bfv[col];
        }

    #pragma unroll
    for (int mt = 0; mt < 4; mt++) {
        #pragma unroll
        for (int h = 0; h < 2; h++) {
            const int seg = g_seg[nbase + wm * 64 + mt * 16 + h * 8 + lr];
            const int base = ((seg * Bn + b) << 9) + eb + we * 16 + 2 * lq;
            #pragma unroll
            for (int nt = 0; nt < 2; nt++) {
                #pragma unroll
                for (int cc = 0; cc < 2; cc++) {
                    const int o = base + nt * 8 + cc;
                    float ev = __expf(cg[mt][nt][h * 2 + cc] + biasg[nt][cc]);
                    atomicAdd(&g_denom[o], ev);
                    atomicAdd(&g_ynum[o], (cf[mt][nt][h * 2 + cc] + biasf[nt][cc]) * ev);
                }
            }
        }
    }
}

// ---------------------------------------------------------------------------
// div, hy (fp32 SIMT), gather — unchanged
// ---------------------------------------------------------------------------
__global__ void div_k() {
    int i = blockIdx.x * blockDim.x + threadIdx.x;
    float4 d = ((const float4*)g_denom)[i];
    float4 a = ((const float4*)g_ynum)[i];
    float4 r;
    r.x = (d.x > 0.f) ? a.x / d.x : 0.f;
    r.y = (d.y > 0.f) ? a.y / d.y : 0.f;
    r.z = (d.z > 0.f) ? a.z / d.z : 0.f;
    r.w = (d.w > 0.f) ? a.w / d.w : 0.f;
    ((float4*)g_ynum)[i] = r;
}

#define HASTR 132
#define HBSTR 68

__global__ __launch_bounds__(256, 2)
void hy_k(const float* __restrict__ Wh, const float* __restrict__ bh)
{
    __shared__ float As[16 * HASTR];
    __shared__ float Bh[16 * HBSTR];

    const int tid = threadIdx.x;
    const int ec  = blockIdx.x;
    const int rr0 = blockIdx.y * 128;
    const int e0  = ec * 64;

    const int tx = tid & 15, ty = tid >> 4;
    const int m0 = ty * 8;
    const int srow = tid & 127, sh = tid >> 7;
    const int we = tid >> 2, wc = tid & 3;

    float acc[8][4];
    #pragma unroll
    for (int i = 0; i < 8; i++)
        #pragma unroll
        for (int j = 0; j < 4; j++) acc[i][j] = 0.f;

    const float4* y4  = (const float4*)g_ynum;
    const float4* wh4 = (const float4*)Wh;

    for (int kc = 0; kc < Dn; kc += 16) {
        const int kq = kc >> 2;
        #pragma unroll
        for (int it = 0; it < 2; it++) {
            int cc = sh * 2 + it;
            float4 v = y4[(size_t)(rr0 + srow) * 128 + kq + cc];
            As[(cc * 4 + 0) * HASTR + srow] = v.x;
            As[(cc * 4 + 1) * HASTR + srow] = v.y;
            As[(cc * 4 + 2) * HASTR + srow] = v.z;
            As[(cc * 4 + 3) * HASTR + srow] = v.w;
        }
        {
            float4 hv = wh4[(size_t)(e0 + we) * 128 + kq + wc];
            Bh[(wc * 4 + 0) * HBSTR + we] = hv.x;
            Bh[(wc * 4 + 1) * HBSTR + we] = hv.y;
            Bh[(wc * 4 + 2) * HBSTR + we] = hv.z;
            Bh[(wc * 4 + 3) * HBSTR + we] = hv.w;
        }
        __syncthreads();

        #pragma unroll
        for (int k = 0; k < 16; k++) {
            float4 a0 = *(const float4*)(As + k * HASTR + m0);
            float4 a1 = *(const float4*)(As + k * HASTR + m0 + 4);
            float4 bv = *(const float4*)(Bh + k * HBSTR + tx * 4);
            float a[8] = {a0.x, a0.y, a0.z, a0.w, a1.x, a1.y, a1.z, a1.w};
            float hv[4] = {bv.x, bv.y, bv.z, bv.w};
            #pragma unroll
            for (int i = 0; i < 8; i++)
                #pragma unroll
                for (int j = 0; j < 4; j++)
                    acc[i][j] += a[i] * hv[j];
        }
        __syncthreads();
    }

    const int ecol = e0 + tx * 4;
    float4 bv;
    bv.x = bh[ecol]; bv.y = bh[ecol + 1]; bv.z = bh[ecol + 2]; bv.w = bh[ecol + 3];
    #pragma unroll
    for (int i = 0; i < 8; i++) {
        float4 v;
        v.x = acc[i][0] + bv.x;
        v.y = acc[i][1] + bv.y;
        v.z = acc[i][2] + bv.z;
        v.w = acc[i][3] + bv.w;
        *(float4*)(g_hy + (size_t)(rr0 + m0 + i) * Dn + ecol) = v;
    }
}

__global__ void gather_k(float4* __restrict__ out)
{
    const int idx = blockIdx.x * 256 + threadIdx.x;
    const int e4 = idx & 127;
    const int nb = idx >> 7;
    const int n  = nb & (Nn - 1);
    const int b  = nb >> 16;
    const int s  = g_seg[n];
    out[idx] = ((const float4*)g_hy)[((s * Bn + b) << 7) + e4];
}

// ---------------------------------------------------------------------------
extern "C" void kernel_launch(void* const* d_in, const int* in_sizes, int n_in,
                              void* d_out, int out_size)
{
    const float* x   = (const float*)d_in[0];
    const int*   ixw = (const int*)d_in[1];
    const float* Wf  = (const float*)d_in[2];
    const float* bf  = (const float*)d_in[3];
    const float* Wg  = (const float*)d_in[4];
    const float* bg  = (const float*)d_in[5];
    const float* Wh  = (const float*)d_in[6];
    const float* bh  = (const float*)d_in[7];

    cudaFuncSetAttribute(main_k, cudaFuncAttributeMaxDynamicSharedMemorySize, SMEM_TOTAL);

    // (0) detect dtype  (1) seg ids + zero accumulators  (2) x/W -> fp16
    detect_k<<<1, 32>>>(ixw);
    segzero_k<<<Nn / 256, 256>>>(ixw);
    xwcvt_k<<<XBLOCKS + (Dn * Dn / 4) / 256, 256>>>(
        (const float4*)x, (const float4*)Wg, (const float4*)Wf);

    // (3) fused dual fp16 GEMM + exp + segment atomic accumulation
    main_k<<<dim3(4, (Bn * Nn) / 128), 512, SMEM_TOTAL>>>(bf, bg);

    // (4) y = ynum/denom   (5) hy = y @ Wh^T + bh   (6) gather
    div_k<<<(Sn * Bn * Dn / 4) / 256, 256>>>();
    hy_k<<<dim3(8, (Sn * Bn) / 128), 256>>>(Wh, bh);
    gather_k<<<(Bn * Nn * 128) / 256, 256>>>((float4*)d_out);

    (void)in_sizes; (void)n_in; (void)out_size;
}